// round 6
// baseline (speedup 1.0000x reference)
#include <cuda_runtime.h>
#include <cooperative_groups.h>
#include <math.h>

namespace cg = cooperative_groups;

#define NB 8
#define N1 384
#define NQ 96                         // float4s per row
#define NPTS (N1*N1)                  // 147456
#define CLUSTER 16
#define ROWS_PER_CTA (N1/CLUSTER)     // 24
#define TPB 384                       // 96 x 4
#define ROWS_PER_PASS 4
#define MWN (ROWS_PER_CTA/ROWS_PER_PASS)  // 6
#define PTS_PER_CTA (ROWS_PER_CTA*N1)     // 9216
#define F4_PER_CTA (PTS_PER_CTA/4)        // 2304
#define F4_ITERS (F4_PER_CTA/TPB)         // 6
#define KMAXI 30
#define NWARPS (TPB/32)               // 12
#define NCH 5

// ---- scratch: __device__ globals (no allocation allowed) ----
__device__ __align__(16) float g_coo[NB][NPTS];
__device__ __align__(16) float g_cmo[NB][NPTS];
__device__ __align__(16) float g_cpo[NB][NPTS];
__device__ __align__(16) float g_com[NB][NPTS];
__device__ __align__(16) float g_cop[NB][NPTS];
__device__ __align__(16) float g_x [NB][NPTS];
__device__ __align__(16) float g_r [NB][NPTS];
__device__ __align__(16) float g_r0[NB][NPTS];
__device__ __align__(16) float g_p [NB][NPTS];
__device__ __align__(16) float g_v [NB][NPTS];
__device__ __align__(16) float g_s [NB][NPTS];
__device__ __align__(16) float g_t [NB][NPTS];

#define AS4(a)  (reinterpret_cast<float4*>(a))
#define CAS4(a) (reinterpret_cast<const float4*>(a))

// Cluster-wide reduction of nv (<=5) per-thread FLOAT partials into identical
// DOUBLE sums in every CTA's s_out[]. Deterministic across CTAs.
__device__ __forceinline__ void cluster_reduce(cg::cluster_group& cluster,
    const float* vals, int nv, double* s_part, double* s_out, int buf)
{
    __shared__ float s_warp[NWARPS*NCH];
    const int tid  = threadIdx.x;
    const int lane = tid & 31;
    const int wid  = tid >> 5;
    for (int c = 0; c < nv; c++) {
        float vv = vals[c];
        #pragma unroll
        for (int o = 16; o > 0; o >>= 1) vv += __shfl_down_sync(0xffffffffu, vv, o);
        if (lane == 0) s_warp[wid*NCH + c] = vv;
    }
    __syncthreads();
    if (wid == 0) {
        for (int c = 0; c < nv; c++) {
            double vv = (lane < NWARPS) ? (double)s_warp[lane*NCH + c] : 0.0;
            #pragma unroll
            for (int o = 8; o > 0; o >>= 1) vv += __shfl_down_sync(0xffffffffu, vv, o);
            if (lane == 0) s_part[buf*NCH + c] = vv;
        }
    }
    cluster.sync();
    if (tid < CLUSTER) {
        double loc[NCH];
        double* rp = (double*)cluster.map_shared_rank((void*)s_part, tid);
        for (int c = 0; c < nv; c++) loc[c] = rp[buf*NCH + c];
        for (int c = 0; c < nv; c++) {
            double vv = loc[c];
            #pragma unroll
            for (int o = 8; o > 0; o >>= 1) vv += __shfl_down_sync(0xffffu, vv, o);
            if (tid == 0) s_out[c] = vv;
        }
    }
    __syncthreads();
}

// tile sweep with halos: each thread owns one float4 (q=tx) in rows w0+ty, step 4.
#define FOR4(...) \
    _Pragma("unroll 2") \
    for (int mw = 0; mw < MWN; mw++) { \
        const int w   = w0 + ty + mw*ROWS_PER_PASS; \
        const int q   = tx; \
        const int nf  = w*NQ + q; \
        const int n   = w*N1 + q*4; \
        const int wmr = (w > 0)      ? w - 1 : w; \
        const int wpr = (w < N1 - 1) ? w + 1 : w; \
        const int nfm = wmr*NQ + q; \
        const int nfp = wpr*NQ + q; \
        (void)n; (void)nfm; (void)nfp; \
        __VA_ARGS__ \
    }

// flat pointwise sweep (no halos): fully coalesced, nf strides by TPB.
#define FORFLAT(...) \
    _Pragma("unroll") \
    for (int k2 = 0; k2 < F4_ITERS; k2++) { \
        const int nf = w0*NQ + k2*TPB + tid; \
        __VA_ARGS__ \
    }

#define STENCIL4(OUT, koo, kmo, kpo, kom, kop, fc, fl, fr, fm, fp) \
    OUT.x = koo.x*fc.x + kmo.x*fl   + kom.x*fm.x + kop.x*fp.x + kpo.x*fc.y; \
    OUT.y = koo.y*fc.y + kmo.y*fc.x + kom.y*fm.y + kop.y*fp.y + kpo.y*fc.z; \
    OUT.z = koo.z*fc.z + kmo.z*fc.y + kom.z*fm.z + kop.z*fp.z + kpo.z*fc.w; \
    OUT.w = koo.w*fc.w + kmo.w*fc.z + kom.w*fm.w + kop.w*fp.w + kpo.w*fr;

#define DOT4(a,b) ((a).x*(b).x + (a).y*(b).y + (a).z*(b).z + (a).w*(b).w)

__global__ void __launch_bounds__(TPB,1)
bicg_solver(const float* __restrict__ Vg, const float* __restrict__ M1g,
            const float* __restrict__ M2g, float* __restrict__ outg)
{
    cg::cluster_group cluster = cg::this_cluster();
    const int tid   = threadIdx.x;
    const int rank  = cluster.block_rank();
    const int batch = blockIdx.x / CLUSTER;
    const int tx = tid % NQ;
    const int ty = tid / NQ;
    const int w0 = rank * ROWS_PER_CTA;

    const float* __restrict__ Vb  = Vg  + batch*NPTS;
    const float* __restrict__ M1b = M1g + batch*NPTS;
    const float* __restrict__ M2b = M2g + batch*NPTS;
    float* __restrict__ coo = g_coo[batch];
    float* __restrict__ cmo = g_cmo[batch];
    float* __restrict__ cpo = g_cpo[batch];
    float* __restrict__ com = g_com[batch];
    float* __restrict__ cop = g_cop[batch];
    float* __restrict__ x   = g_x [batch];
    float* __restrict__ r   = g_r [batch];
    float* __restrict__ r0  = g_r0[batch];
    float* __restrict__ p   = g_p [batch];
    float* __restrict__ v   = g_v [batch];
    float* __restrict__ s   = g_s [batch];
    float* __restrict__ t   = g_t [batch];

    __shared__ double s_part[2*NCH];
    __shared__ double s_out[NCH];
    int red_idx = 0;
    float vals[NCH];

    // ---------- mean(V_batch) ----------
    {
        float acc = 0.0f;
        const float4* vc4 = CAS4(Vb) + rank*(PTS_PER_CTA/4);
        #pragma unroll
        for (int k2 = 0; k2 < F4_ITERS; k2++) {
            float4 vv = vc4[k2*TPB + tid];
            acc += (vv.x + vv.y) + (vv.z + vv.w);
        }
        vals[0] = acc;
        cluster_reduce(cluster, vals, 1, s_part, s_out, red_idx & 1); red_idx++;
    }
    const float bval = (float)(s_out[0] * (1.0/(double)NPTS)) + 1.0f;

    // ---------- stencil coefficients + init (x=bval, p=r=r0=b-Ax0) ----------
    float accp = 0.0f;
    FOR4({
        float4 Vc = CAS4(Vb)[nf];
        float4 Vm = CAS4(Vb)[nfm];
        float4 Vp = CAS4(Vb)[nfp];
        float  vl = (q > 0)     ? Vb[n-1] : 0.0f;
        float  vr = (q < NQ-1)  ? Vb[n+4] : 0.0f;
        float4 M1c = CAS4(M1b)[nf];
        float  m1l = (q > 0)    ? M1b[n-1] : 0.0f;
        float4 M2c = CAS4(M2b)[nf];
        float4 M2m = CAS4(M2b)[nfm];
        float cv[6]  = {vl, Vc.x, Vc.y, Vc.z, Vc.w, vr};
        float m1a[5] = {m1l, M1c.x, M1c.y, M1c.z, M1c.w};
        float vmv[4] = {Vm.x, Vm.y, Vm.z, Vm.w};
        float vpv[4] = {Vp.x, Vp.y, Vp.z, Vp.w};
        float m2c[4] = {M2c.x, M2c.y, M2c.z, M2c.w};
        float m2m[4] = {M2m.x, M2m.y, M2m.z, M2m.w};
        float4 koo, kmo, kpo, kom, kop, pn4, x4;
        float* koo_ = &koo.x; float* kmo_ = &kmo.x; float* kpo_ = &kpo.x;
        float* kom_ = &kom.x; float* kop_ = &kop.x; float* pn_ = &pn4.x; float* x_ = &x4.x;
        #pragma unroll
        for (int i = 0; i < 4; i++) {
            int u = q*4 + i;
            float d1p = 0.f, d1m = 0.f, d2p = 0.f, d2m = 0.f;
            if (u < N1-1) d1p = (cv[i+2]-cv[i+1])/(0.5f*(cv[i+2]+cv[i+1])+1.0f)*m1a[i+1];
            if (u > 0)    d1m = (cv[i+1]-cv[i]  )/(0.5f*(cv[i+1]+cv[i]  )+1.0f)*m1a[i];
            if (w < N1-1) d2p = (vpv[i]-cv[i+1] )/(0.5f*(vpv[i]+cv[i+1] )+1.0f)*m2c[i];
            if (w > 0)    d2m = (cv[i+1]-vmv[i] )/(0.5f*(cv[i+1]+vmv[i] )+1.0f)*m2m[i];
            float a_po = -10.0f + 5.0f*d1p;
            float a_mo = -10.0f - 5.0f*d1m;
            float a_op = -10.0f + 5.0f*d2p;
            float a_om = -10.0f - 5.0f*d2m;
            float a_oo = 81.0f + a_po + a_mo + a_op + a_om;
            kpo_[i] = a_po; kmo_[i] = a_mo; kop_[i] = a_op; kom_[i] = a_om; koo_[i] = a_oo;
            float pn = bval*(1.0f - (a_oo + a_mo + a_po + a_om + a_op));
            pn_[i] = pn; x_[i] = bval;
            accp += pn * pn;
        }
        AS4(coo)[nf] = koo; AS4(cmo)[nf] = kmo; AS4(cpo)[nf] = kpo;
        AS4(com)[nf] = kom; AS4(cop)[nf] = kop;
        AS4(p)[nf] = pn4; AS4(r)[nf] = pn4; AS4(r0)[nf] = pn4; AS4(x)[nf] = x4;
    })
    vals[0] = accp;
    cluster_reduce(cluster, vals, 1, s_part, s_out, red_idx & 1); red_idx++;
    double pp = s_out[0];
    double r0_abs = (pp > 0.0) ? sqrt(pp) : 0.0;
    double r_abs  = r0_abs;
    double srr0   = pp;            // <r, r0> carried across iterations
    const double thr = 1e-9 * (double)NPTS;

    // ---------- BiCGSTAB main loop ----------
    for (int it = 0; it < KMAXI; it++) {
        if (!(r_abs > thr)) break;

        // P1: v = A p; sigma = <v,r0>, ||v||^2
        float a0 = 0.f, a1 = 0.f;
        FOR4({
            float4 pc = CAS4(p)[nf];
            float4 pm = CAS4(p)[nfm];
            float4 pq = CAS4(p)[nfp];
            float  pl = (q > 0)    ? p[n-1] : pc.x;
            float  pr = (q < NQ-1) ? p[n+4] : pc.w;
            float4 koo = CAS4(coo)[nf], kmo = CAS4(cmo)[nf], kpo = CAS4(cpo)[nf];
            float4 kom = CAS4(com)[nf], kop = CAS4(cop)[nf];
            float4 vn;
            STENCIL4(vn, koo, kmo, kpo, kom, kop, pc, pl, pr, pm, pq);
            AS4(v)[nf] = vn;
            float4 r04 = CAS4(r0)[nf];
            a0 += DOT4(vn, r04);
            a1 += DOT4(vn, vn);
        })
        vals[0] = a0; vals[1] = a1;
        cluster_reduce(cluster, vals, 2, s_part, s_out, red_idx & 1); red_idx++;
        double sigma = s_out[0];
        double vsq   = s_out[1];
        double v_abs = (vsq > 0.0) ? sqrt(vsq) : 0.0;

        if (sigma <= 1e-9 * v_abs * r0_abs) {    // restart (R1)
            float ar = 0.f;
            FOR4({
                float4 xc = CAS4(x)[nf];
                float4 xm = CAS4(x)[nfm];
                float4 xq = CAS4(x)[nfp];
                float  xl = (q > 0)    ? x[n-1] : xc.x;
                float  xr = (q < NQ-1) ? x[n+4] : xc.w;
                float4 koo = CAS4(coo)[nf], kmo = CAS4(cmo)[nf], kpo = CAS4(cpo)[nf];
                float4 kom = CAS4(com)[nf], kop = CAS4(cop)[nf];
                float4 ax;
                STENCIL4(ax, koo, kmo, kpo, kom, kop, xc, xl, xr, xm, xq);
                float4 pn;
                pn.x = bval - ax.x; pn.y = bval - ax.y; pn.z = bval - ax.z; pn.w = bval - ax.w;
                AS4(p)[nf] = pn; AS4(r)[nf] = pn; AS4(r0)[nf] = pn;
                ar += DOT4(pn, pn);
            })
            vals[0] = ar;
            cluster_reduce(cluster, vals, 1, s_part, s_out, red_idx & 1); red_idx++;
            double rr = s_out[0];
            r0_abs = (rr > 0.0) ? sqrt(rr) : 0.0;
            r_abs  = r0_abs;
            srr0   = rr;
            continue;
        }

        double alpha  = srr0 / sigma;
        float  af = (float)alpha;

        // P2 (fused): s = r - alpha*v (halos on the fly), t = A s;
        // acc ||s||^2, <t,s>, <t,t>, <s,r0>, <t,r0>
        float b0 = 0.f, b1 = 0.f, b2 = 0.f, b3 = 0.f, b4 = 0.f;
        FOR4({
            float4 rc = CAS4(r)[nf],  vc = CAS4(v)[nf];
            float4 rm = CAS4(r)[nfm], vm = CAS4(v)[nfm];
            float4 rq = CAS4(r)[nfp], vq = CAS4(v)[nfp];
            float4 sc, sm, sq;
            sc.x = rc.x - af*vc.x; sc.y = rc.y - af*vc.y; sc.z = rc.z - af*vc.z; sc.w = rc.w - af*vc.w;
            sm.x = rm.x - af*vm.x; sm.y = rm.y - af*vm.y; sm.z = rm.z - af*vm.z; sm.w = rm.w - af*vm.w;
            sq.x = rq.x - af*vq.x; sq.y = rq.y - af*vq.y; sq.z = rq.z - af*vq.z; sq.w = rq.w - af*vq.w;
            float sl = (q > 0)    ? (r[n-1] - af*v[n-1]) : sc.x;
            float sr = (q < NQ-1) ? (r[n+4] - af*v[n+4]) : sc.w;
            float4 koo = CAS4(coo)[nf], kmo = CAS4(cmo)[nf], kpo = CAS4(cpo)[nf];
            float4 kom = CAS4(com)[nf], kop = CAS4(cop)[nf];
            float4 tn;
            STENCIL4(tn, koo, kmo, kpo, kom, kop, sc, sl, sr, sm, sq);
            AS4(s)[nf] = sc; AS4(t)[nf] = tn;
            float4 r04 = CAS4(r0)[nf];
            b0 += DOT4(sc, sc);
            b1 += DOT4(tn, sc);
            b2 += DOT4(tn, tn);
            b3 += DOT4(sc, r04);
            b4 += DOT4(tn, r04);
        })
        vals[0]=b0; vals[1]=b1; vals[2]=b2; vals[3]=b3; vals[4]=b4;
        cluster_reduce(cluster, vals, 5, s_part, s_out, red_idx & 1); red_idx++;
        double ssum = s_out[0];
        double tsv  = s_out[1];
        double ttv  = s_out[2];
        double sr0  = s_out[3];
        double tr0  = s_out[4];
        double s_abs = (ssum > 0.0) ? sqrt(ssum) : 0.0;

        if (s_abs <= thr) {                      // C2/C3: converged
            FORFLAT({
                float4 xc = CAS4(x)[nf], pc = CAS4(p)[nf];
                xc.x += af*pc.x; xc.y += af*pc.y; xc.z += af*pc.z; xc.w += af*pc.w;
                AS4(x)[nf] = xc;
            })
            r_abs = s_abs;
            break;
        }

        double omega = tsv / ttv;
        float  of = (float)omega;

        // Analytic P3 scalars (no reduction needed):
        double rnr0 = sr0 - omega * tr0;                       // <r_new, r0>
        double rn2  = ssum - 2.0*omega*tsv + omega*omega*ttv;  // ||r_new||^2
        double beta = (alpha / omega) * (rnr0 / srr0);
        float  bf = (float)beta;
        srr0  = rnr0;
        r_abs = (rn2 > 0.0) ? sqrt(rn2) : 0.0;

        // P3 (fused update, pointwise, flat/coalesced):
        // x += alpha*p + omega*s;  r = s - omega*t;  p = r + beta*(p - omega*v)
        FORFLAT({
            float4 xc = CAS4(x)[nf], pc = CAS4(p)[nf];
            float4 sc = CAS4(s)[nf], tc = CAS4(t)[nf], vc = CAS4(v)[nf];
            float4 xn, rn, pn;
            xn.x = xc.x + af*pc.x + of*sc.x;  rn.x = sc.x - of*tc.x;  pn.x = rn.x + bf*(pc.x - of*vc.x);
            xn.y = xc.y + af*pc.y + of*sc.y;  rn.y = sc.y - of*tc.y;  pn.y = rn.y + bf*(pc.y - of*vc.y);
            xn.z = xc.z + af*pc.z + of*sc.z;  rn.z = sc.z - of*tc.z;  pn.z = rn.z + bf*(pc.z - of*vc.z);
            xn.w = xc.w + af*pc.w + of*sc.w;  rn.w = sc.w - of*tc.w;  pn.w = rn.w + bf*(pc.w - of*vc.w);
            AS4(x)[nf] = xn; AS4(r)[nf] = rn; AS4(p)[nf] = pn;
        })
        cluster.sync();   // order p/r writes before next iteration's halo reads
    }

    cluster.sync();       // x fully written & visible across the cluster

    // ---------- output: out[b][i][j] = x[j*384 + i] (transposed frame) ----------
    float* outb = outg + batch*NPTS;
    #pragma unroll 1
    for (int k2 = 0; k2 < PTS_PER_CTA/TPB; k2++) {
        int lin = k2*TPB + tid;
        int ul  = lin / N1;
        int wq  = lin - ul*N1;
        int uo  = w0 + ul;
        outb[uo*N1 + wq] = x[wq*N1 + uo];
    }
}

extern "C" void kernel_launch(void* const* d_in, const int* in_sizes, int n_in,
                              void* d_out, int out_size)
{
    const float* V  = (const float*)d_in[0];
    const float* M1 = (const float*)d_in[1];
    const float* M2 = (const float*)d_in[2];
    float* out = (float*)d_out;

    cudaFuncSetAttribute(bicg_solver, cudaFuncAttributeNonPortableClusterSizeAllowed, 1);

    cudaLaunchConfig_t cfg = {};
    cfg.gridDim  = dim3(NB*CLUSTER, 1, 1);
    cfg.blockDim = dim3(TPB, 1, 1);
    cfg.dynamicSmemBytes = 0;
    cudaLaunchAttribute attrs[1];
    attrs[0].id = cudaLaunchAttributeClusterDimension;
    attrs[0].val.clusterDim.x = CLUSTER;
    attrs[0].val.clusterDim.y = 1;
    attrs[0].val.clusterDim.z = 1;
    cfg.attrs = attrs;
    cfg.numAttrs = 1;
    cudaLaunchKernelEx(&cfg, bicg_solver, V, M1, M2, out);
}

// round 8
// speedup vs baseline: 1.6936x; 1.6936x over previous
#include <cuda_runtime.h>
#include <cooperative_groups.h>
#include <math.h>

namespace cg = cooperative_groups;

#define NB 8
#define N1 384
#define NQ 96                         // float4s per row
#define NPTS (N1*N1)                  // 147456
#define CLUSTER 16
#define ROWS_PER_CTA (N1/CLUSTER)     // 24
#define TPB 384                       // 96 x 4
#define ROWS_PER_PASS 4
#define MWN (ROWS_PER_CTA/ROWS_PER_PASS)  // 6
#define PTS_PER_CTA (ROWS_PER_CTA*N1)     // 9216
#define F4_PER_CTA (PTS_PER_CTA/4)        // 2304
#define F4_ITERS (F4_PER_CTA/TPB)         // 6
#define KMAXI 30
#define NWARPS (TPB/32)               // 12
#define NCH 4
#define SMEM_COEF_BYTES (5*F4_PER_CTA*16) // 184320

// ---- scratch: __device__ globals (no allocation allowed) ----
__device__ __align__(16) float g_x [NB][NPTS];
__device__ __align__(16) float g_r [NB][NPTS];
__device__ __align__(16) float g_r0[NB][NPTS];
__device__ __align__(16) float g_p [NB][NPTS];
__device__ __align__(16) float g_v [NB][NPTS];
__device__ __align__(16) float g_s [NB][NPTS];
__device__ __align__(16) float g_t [NB][NPTS];

#define AS4(a)  (reinterpret_cast<float4*>(a))
#define CAS4(a) (reinterpret_cast<const float4*>(a))

// Cluster-wide reduction of nv (<=3) per-thread FLOAT partials into identical
// DOUBLE sums in every CTA's s_out[]. Deterministic across CTAs.
__device__ __forceinline__ void cluster_reduce(cg::cluster_group& cluster,
    const float* vals, int nv, double* s_part, double* s_out, int buf)
{
    __shared__ float s_warp[NWARPS*NCH];
    const int tid  = threadIdx.x;
    const int lane = tid & 31;
    const int wid  = tid >> 5;
    for (int c = 0; c < nv; c++) {
        float vv = vals[c];
        #pragma unroll
        for (int o = 16; o > 0; o >>= 1) vv += __shfl_down_sync(0xffffffffu, vv, o);
        if (lane == 0) s_warp[wid*NCH + c] = vv;
    }
    __syncthreads();
    if (wid == 0) {
        for (int c = 0; c < nv; c++) {
            double vv = (lane < NWARPS) ? (double)s_warp[lane*NCH + c] : 0.0;
            #pragma unroll
            for (int o = 8; o > 0; o >>= 1) vv += __shfl_down_sync(0xffffffffu, vv, o);
            if (lane == 0) s_part[buf*NCH + c] = vv;
        }
    }
    cluster.sync();
    if (tid < CLUSTER) {
        double loc[NCH];
        double* rp = (double*)cluster.map_shared_rank((void*)s_part, tid);
        for (int c = 0; c < nv; c++) loc[c] = rp[buf*NCH + c];
        for (int c = 0; c < nv; c++) {
            double vv = loc[c];
            #pragma unroll
            for (int o = 8; o > 0; o >>= 1) vv += __shfl_down_sync(0xffffu, vv, o);
            if (tid == 0) s_out[c] = vv;
        }
    }
    __syncthreads();
}

// tile sweep with halos: each thread owns one float4 (q=tx) in rows w0+ty, step 4.
// lf = CTA-local float4 index (for smem coefficient access).
#define FOR4(...) \
    _Pragma("unroll 2") \
    for (int mw = 0; mw < MWN; mw++) { \
        const int w   = w0 + ty + mw*ROWS_PER_PASS; \
        const int q   = tx; \
        const int nf  = w*NQ + q; \
        const int lf  = (w - w0)*NQ + q; \
        const int n   = w*N1 + q*4; \
        const int wmr = (w > 0)      ? w - 1 : w; \
        const int wpr = (w < N1 - 1) ? w + 1 : w; \
        const int nfm = wmr*NQ + q; \
        const int nfp = wpr*NQ + q; \
        (void)n; (void)nfm; (void)nfp; (void)lf; \
        __VA_ARGS__ \
    }

// flat pointwise sweep (no halos): fully coalesced, nf strides by TPB.
#define FORFLAT(...) \
    _Pragma("unroll") \
    for (int k2 = 0; k2 < F4_ITERS; k2++) { \
        const int nf = w0*NQ + k2*TPB + tid; \
        __VA_ARGS__ \
    }

#define STENCIL4(OUT, koo, kmo, kpo, kom, kop, fc, fl, fr, fm, fp) \
    OUT.x = koo.x*fc.x + kmo.x*fl   + kom.x*fm.x + kop.x*fp.x + kpo.x*fc.y; \
    OUT.y = koo.y*fc.y + kmo.y*fc.x + kom.y*fm.y + kop.y*fp.y + kpo.y*fc.z; \
    OUT.z = koo.z*fc.z + kmo.z*fc.y + kom.z*fm.z + kop.z*fp.z + kpo.z*fc.w; \
    OUT.w = koo.w*fc.w + kmo.w*fc.z + kom.w*fm.w + kop.w*fp.w + kpo.w*fr;

#define DOT4(a,b) ((a).x*(b).x + (a).y*(b).y + (a).z*(b).z + (a).w*(b).w)

__global__ void __launch_bounds__(TPB,1)
bicg_solver(const float* __restrict__ Vg, const float* __restrict__ M1g,
            const float* __restrict__ M2g, float* __restrict__ outg)
{
    cg::cluster_group cluster = cg::this_cluster();
    const int tid   = threadIdx.x;
    const int rank  = cluster.block_rank();
    const int batch = blockIdx.x / CLUSTER;
    const int tx = tid % NQ;
    const int ty = tid / NQ;
    const int w0 = rank * ROWS_PER_CTA;

    const float* __restrict__ Vb  = Vg  + batch*NPTS;
    const float* __restrict__ M1b = M1g + batch*NPTS;
    const float* __restrict__ M2b = M2g + batch*NPTS;
    float* __restrict__ x   = g_x [batch];
    float* __restrict__ r   = g_r [batch];
    float* __restrict__ r0  = g_r0[batch];
    float* __restrict__ p   = g_p [batch];
    float* __restrict__ v   = g_v [batch];
    float* __restrict__ s   = g_s [batch];
    float* __restrict__ t   = g_t [batch];

    // CTA-private stencil coefficients live ONLY in shared memory:
    // immune to the per-cluster.sync L1 flush, LDS latency instead of L2.
    extern __shared__ float4 cs[];
    float4* __restrict__ Scoo = cs;
    float4* __restrict__ Scmo = cs + 1*F4_PER_CTA;
    float4* __restrict__ Scpo = cs + 2*F4_PER_CTA;
    float4* __restrict__ Scom = cs + 3*F4_PER_CTA;
    float4* __restrict__ Scop = cs + 4*F4_PER_CTA;

    __shared__ double s_part[2*NCH];
    __shared__ double s_out[NCH];
    int red_idx = 0;
    float vals[NCH];

    // ---------- mean(V_batch) ----------
    {
        float acc = 0.0f;
        const float4* vc4 = CAS4(Vb) + rank*F4_PER_CTA;
        #pragma unroll
        for (int k2 = 0; k2 < F4_ITERS; k2++) {
            float4 vv = vc4[k2*TPB + tid];
            acc += (vv.x + vv.y) + (vv.z + vv.w);
        }
        vals[0] = acc;
        cluster_reduce(cluster, vals, 1, s_part, s_out, red_idx & 1); red_idx++;
    }
    const float bval = (float)(s_out[0] * (1.0/(double)NPTS)) + 1.0f;

    // ---------- stencil coefficients (smem) + init (x=bval, p=r=r0=b-Ax0) ----------
    float accp = 0.0f;
    FOR4({
        float4 Vc = CAS4(Vb)[nf];
        float4 Vm = CAS4(Vb)[nfm];
        float4 Vp = CAS4(Vb)[nfp];
        float  vl = (q > 0)     ? Vb[n-1] : 0.0f;
        float  vr = (q < NQ-1)  ? Vb[n+4] : 0.0f;
        float4 M1c = CAS4(M1b)[nf];
        float  m1l = (q > 0)    ? M1b[n-1] : 0.0f;
        float4 M2c = CAS4(M2b)[nf];
        float4 M2m = CAS4(M2b)[nfm];
        float cv[6]  = {vl, Vc.x, Vc.y, Vc.z, Vc.w, vr};
        float m1a[5] = {m1l, M1c.x, M1c.y, M1c.z, M1c.w};
        float vmv[4] = {Vm.x, Vm.y, Vm.z, Vm.w};
        float vpv[4] = {Vp.x, Vp.y, Vp.z, Vp.w};
        float m2c[4] = {M2c.x, M2c.y, M2c.z, M2c.w};
        float m2m[4] = {M2m.x, M2m.y, M2m.z, M2m.w};
        float4 koo, kmo, kpo, kom, kop, pn4, x4;
        float* koo_ = &koo.x; float* kmo_ = &kmo.x; float* kpo_ = &kpo.x;
        float* kom_ = &kom.x; float* kop_ = &kop.x; float* pn_ = &pn4.x; float* x_ = &x4.x;
        #pragma unroll
        for (int i = 0; i < 4; i++) {
            int u = q*4 + i;
            float d1p = 0.f, d1m = 0.f, d2p = 0.f, d2m = 0.f;
            if (u < N1-1) d1p = (cv[i+2]-cv[i+1])/(0.5f*(cv[i+2]+cv[i+1])+1.0f)*m1a[i+1];
            if (u > 0)    d1m = (cv[i+1]-cv[i]  )/(0.5f*(cv[i+1]+cv[i]  )+1.0f)*m1a[i];
            if (w < N1-1) d2p = (vpv[i]-cv[i+1] )/(0.5f*(vpv[i]+cv[i+1] )+1.0f)*m2c[i];
            if (w > 0)    d2m = (cv[i+1]-vmv[i] )/(0.5f*(cv[i+1]+vmv[i] )+1.0f)*m2m[i];
            float a_po = -10.0f + 5.0f*d1p;
            float a_mo = -10.0f - 5.0f*d1m;
            float a_op = -10.0f + 5.0f*d2p;
            float a_om = -10.0f - 5.0f*d2m;
            float a_oo = 81.0f + a_po + a_mo + a_op + a_om;
            kpo_[i] = a_po; kmo_[i] = a_mo; kop_[i] = a_op; kom_[i] = a_om; koo_[i] = a_oo;
            float pn = bval*(1.0f - (a_oo + a_mo + a_po + a_om + a_op));
            pn_[i] = pn; x_[i] = bval;
            accp += pn * pn;
        }
        Scoo[lf] = koo; Scmo[lf] = kmo; Scpo[lf] = kpo;
        Scom[lf] = kom; Scop[lf] = kop;
        AS4(p)[nf] = pn4; AS4(r)[nf] = pn4; AS4(r0)[nf] = pn4; AS4(x)[nf] = x4;
    })
    vals[0] = accp;
    cluster_reduce(cluster, vals, 1, s_part, s_out, red_idx & 1); red_idx++;
    double pp = s_out[0];
    double r0_abs = (pp > 0.0) ? sqrt(pp) : 0.0;
    double r_abs  = r0_abs;
    double srr0   = pp;            // <r, r0> carried across iterations
    const double thr = 1e-9 * (double)NPTS;

    // ---------- BiCGSTAB main loop ----------
    for (int it = 0; it < KMAXI; it++) {
        if (!(r_abs > thr)) break;

        // P1: v = A p; sigma = <v,r0>, ||v||^2
        float a0 = 0.f, a1 = 0.f;
        FOR4({
            float4 pc = CAS4(p)[nf];
            float4 pm = CAS4(p)[nfm];
            float4 pq = CAS4(p)[nfp];
            float  pl = (q > 0)    ? p[n-1] : pc.x;
            float  pr = (q < NQ-1) ? p[n+4] : pc.w;
            float4 koo = Scoo[lf], kmo = Scmo[lf], kpo = Scpo[lf];
            float4 kom = Scom[lf], kop = Scop[lf];
            float4 vn;
            STENCIL4(vn, koo, kmo, kpo, kom, kop, pc, pl, pr, pm, pq);
            AS4(v)[nf] = vn;
            float4 r04 = CAS4(r0)[nf];
            a0 += DOT4(vn, r04);
            a1 += DOT4(vn, vn);
        })
        vals[0] = a0; vals[1] = a1;
        cluster_reduce(cluster, vals, 2, s_part, s_out, red_idx & 1); red_idx++;
        double sigma = s_out[0];
        double vsq   = s_out[1];
        double v_abs = (vsq > 0.0) ? sqrt(vsq) : 0.0;

        if (sigma <= 1e-9 * v_abs * r0_abs) {    // restart (R1)
            float ar = 0.f;
            FOR4({
                float4 xc = CAS4(x)[nf];
                float4 xm = CAS4(x)[nfm];
                float4 xq = CAS4(x)[nfp];
                float  xl = (q > 0)    ? x[n-1] : xc.x;
                float  xr = (q < NQ-1) ? x[n+4] : xc.w;
                float4 koo = Scoo[lf], kmo = Scmo[lf], kpo = Scpo[lf];
                float4 kom = Scom[lf], kop = Scop[lf];
                float4 ax;
                STENCIL4(ax, koo, kmo, kpo, kom, kop, xc, xl, xr, xm, xq);
                float4 pn;
                pn.x = bval - ax.x; pn.y = bval - ax.y; pn.z = bval - ax.z; pn.w = bval - ax.w;
                AS4(p)[nf] = pn; AS4(r)[nf] = pn; AS4(r0)[nf] = pn;
                ar += DOT4(pn, pn);
            })
            vals[0] = ar;
            cluster_reduce(cluster, vals, 1, s_part, s_out, red_idx & 1); red_idx++;
            double rr = s_out[0];
            r0_abs = (rr > 0.0) ? sqrt(rr) : 0.0;
            r_abs  = r0_abs;
            srr0   = rr;
            continue;
        }

        double alpha  = srr0 / sigma;
        float  af = (float)alpha;

        // P2 (fused): s = r - alpha*v (halos on the fly), t = A s;
        // acc ||s||^2, <t,s>, <t,t>
        float b0 = 0.f, b1 = 0.f, b2 = 0.f;
        FOR4({
            float4 rc = CAS4(r)[nf],  vc = CAS4(v)[nf];
            float4 rm = CAS4(r)[nfm], vm = CAS4(v)[nfm];
            float4 rq = CAS4(r)[nfp], vq = CAS4(v)[nfp];
            float4 sc, sm, sq;
            sc.x = rc.x - af*vc.x; sc.y = rc.y - af*vc.y; sc.z = rc.z - af*vc.z; sc.w = rc.w - af*vc.w;
            sm.x = rm.x - af*vm.x; sm.y = rm.y - af*vm.y; sm.z = rm.z - af*vm.z; sm.w = rm.w - af*vm.w;
            sq.x = rq.x - af*vq.x; sq.y = rq.y - af*vq.y; sq.z = rq.z - af*vq.z; sq.w = rq.w - af*vq.w;
            float sl = (q > 0)    ? (r[n-1] - af*v[n-1]) : sc.x;
            float sr = (q < NQ-1) ? (r[n+4] - af*v[n+4]) : sc.w;
            float4 koo = Scoo[lf], kmo = Scmo[lf], kpo = Scpo[lf];
            float4 kom = Scom[lf], kop = Scop[lf];
            float4 tn;
            STENCIL4(tn, koo, kmo, kpo, kom, kop, sc, sl, sr, sm, sq);
            AS4(s)[nf] = sc; AS4(t)[nf] = tn;
            b0 += DOT4(sc, sc);
            b1 += DOT4(tn, sc);
            b2 += DOT4(tn, tn);
        })
        vals[0] = b0; vals[1] = b1; vals[2] = b2;
        cluster_reduce(cluster, vals, 3, s_part, s_out, red_idx & 1); red_idx++;
        double ssum = s_out[0];
        double tsv  = s_out[1];
        double ttv  = s_out[2];
        double s_abs = (ssum > 0.0) ? sqrt(ssum) : 0.0;

        if (s_abs <= thr) {                      // C2/C3: converged
            FORFLAT({
                float4 xc = CAS4(x)[nf], pc = CAS4(p)[nf];
                xc.x += af*pc.x; xc.y += af*pc.y; xc.z += af*pc.z; xc.w += af*pc.w;
                AS4(x)[nf] = xc;
            })
            r_abs = s_abs;
            break;
        }

        double omega = tsv / ttv;
        float  of = (float)omega;

        // P3: x += alpha*p + omega*s; r = s - omega*t; acc <r,r0>, ||r||^2
        float c0a = 0.f, c1a = 0.f;
        FORFLAT({
            float4 xc = CAS4(x)[nf], pc = CAS4(p)[nf];
            float4 sc = CAS4(s)[nf], tc = CAS4(t)[nf];
            float4 r04 = CAS4(r0)[nf];
            float4 xn, rn;
            xn.x = xc.x + af*pc.x + of*sc.x;  rn.x = sc.x - of*tc.x;
            xn.y = xc.y + af*pc.y + of*sc.y;  rn.y = sc.y - of*tc.y;
            xn.z = xc.z + af*pc.z + of*sc.z;  rn.z = sc.z - of*tc.z;
            xn.w = xc.w + af*pc.w + of*sc.w;  rn.w = sc.w - of*tc.w;
            AS4(x)[nf] = xn; AS4(r)[nf] = rn;
            c0a += DOT4(rn, r04);
            c1a += DOT4(rn, rn);
        })
        vals[0] = c0a; vals[1] = c1a;
        cluster_reduce(cluster, vals, 2, s_part, s_out, red_idx & 1); red_idx++;
        double rnr0 = s_out[0], rn2 = s_out[1];
        double beta = (alpha / omega) * (rnr0 / srr0);
        float  bf = (float)beta;
        srr0  = rnr0;
        r_abs = (rn2 > 0.0) ? sqrt(rn2) : 0.0;

        // P4: p = r + beta*(p - omega*v)
        FORFLAT({
            float4 rc = CAS4(r)[nf], pc = CAS4(p)[nf], vc = CAS4(v)[nf];
            float4 pn;
            pn.x = rc.x + bf*(pc.x - of*vc.x);
            pn.y = rc.y + bf*(pc.y - of*vc.y);
            pn.z = rc.z + bf*(pc.z - of*vc.z);
            pn.w = rc.w + bf*(pc.w - of*vc.w);
            AS4(p)[nf] = pn;
        })
        cluster.sync();   // order p/r writes before next iteration's halo reads
    }

    cluster.sync();       // x fully written & visible across the cluster

    // ---------- output: out[b][i][j] = x[j*384 + i] (transposed frame) ----------
    float* outb = outg + batch*NPTS;
    #pragma unroll 1
    for (int k2 = 0; k2 < PTS_PER_CTA/TPB; k2++) {
        int lin = k2*TPB + tid;
        int ul  = lin / N1;
        int wq  = lin - ul*N1;
        int uo  = w0 + ul;
        outb[uo*N1 + wq] = x[wq*N1 + uo];
    }
}

extern "C" void kernel_launch(void* const* d_in, const int* in_sizes, int n_in,
                              void* d_out, int out_size)
{
    const float* V  = (const float*)d_in[0];
    const float* M1 = (const float*)d_in[1];
    const float* M2 = (const float*)d_in[2];
    float* out = (float*)d_out;

    cudaFuncSetAttribute(bicg_solver, cudaFuncAttributeNonPortableClusterSizeAllowed, 1);
    cudaFuncSetAttribute(bicg_solver, cudaFuncAttributeMaxDynamicSharedMemorySize,
                         SMEM_COEF_BYTES);

    cudaLaunchConfig_t cfg = {};
    cfg.gridDim  = dim3(NB*CLUSTER, 1, 1);
    cfg.blockDim = dim3(TPB, 1, 1);
    cfg.dynamicSmemBytes = SMEM_COEF_BYTES;
    cudaLaunchAttribute attrs[1];
    attrs[0].id = cudaLaunchAttributeClusterDimension;
    attrs[0].val.clusterDim.x = CLUSTER;
    attrs[0].val.clusterDim.y = 1;
    attrs[0].val.clusterDim.z = 1;
    cfg.attrs = attrs;
    cfg.numAttrs = 1;
    cudaLaunchKernelEx(&cfg, bicg_solver, V, M1, M2, out);
}

// round 10
// speedup vs baseline: 1.8120x; 1.0699x over previous
#include <cuda_runtime.h>
#include <cooperative_groups.h>
#include <math.h>

namespace cg = cooperative_groups;

#define NB 8
#define N1 384
#define NQ 96                         // float4s per row
#define NPTS (N1*N1)                  // 147456
#define CLUSTER 16
#define ROWS_PER_CTA (N1/CLUSTER)     // 24
#define TPB 384                       // 96 x 4
#define ROWS_PER_PASS 4
#define MWN (ROWS_PER_CTA/ROWS_PER_PASS)  // 6
#define PTS_PER_CTA (ROWS_PER_CTA*N1)     // 9216
#define F4_PER_CTA (PTS_PER_CTA/4)        // 2304
#define F4_ITERS (F4_PER_CTA/TPB)         // 6
#define KMAXI 30
#define NWARPS (TPB/32)               // 12
#define NCH 3
#define SMEM_COEF_BYTES (5*F4_PER_CTA*16) // 184320

// ---- scratch: __device__ globals (no allocation allowed) ----
// s and t no longer exist in global memory (register-resident only).
__device__ __align__(16) float g_x [NB][NPTS];
__device__ __align__(16) float g_r [NB][NPTS];
__device__ __align__(16) float g_r0[NB][NPTS];
__device__ __align__(16) float g_p [NB][NPTS];
__device__ __align__(16) float g_v [NB][NPTS];

#define AS4(a)  (reinterpret_cast<float4*>(a))
#define CAS4(a) (reinterpret_cast<const float4*>(a))

// Cluster-wide reduction of nv (<=3) per-thread FLOAT partials into identical
// DOUBLE sums in every CTA's s_out[]. Deterministic across CTAs.
__device__ __forceinline__ void cluster_reduce(cg::cluster_group& cluster,
    const float* vals, int nv, double* s_part, double* s_out, int buf)
{
    __shared__ float s_warp[NWARPS*NCH];
    const int tid  = threadIdx.x;
    const int lane = tid & 31;
    const int wid  = tid >> 5;
    for (int c = 0; c < nv; c++) {
        float vv = vals[c];
        #pragma unroll
        for (int o = 16; o > 0; o >>= 1) vv += __shfl_down_sync(0xffffffffu, vv, o);
        if (lane == 0) s_warp[wid*NCH + c] = vv;
    }
    __syncthreads();
    if (wid == 0) {
        for (int c = 0; c < nv; c++) {
            double vv = (lane < NWARPS) ? (double)s_warp[lane*NCH + c] : 0.0;
            #pragma unroll
            for (int o = 8; o > 0; o >>= 1) vv += __shfl_down_sync(0xffffffffu, vv, o);
            if (lane == 0) s_part[buf*NCH + c] = vv;
        }
    }
    cluster.sync();
    if (tid < CLUSTER) {
        double loc[NCH];
        double* rp = (double*)cluster.map_shared_rank((void*)s_part, tid);
        for (int c = 0; c < nv; c++) loc[c] = rp[buf*NCH + c];
        for (int c = 0; c < nv; c++) {
            double vv = loc[c];
            #pragma unroll
            for (int o = 8; o > 0; o >>= 1) vv += __shfl_down_sync(0xffffu, vv, o);
            if (tid == 0) s_out[c] = vv;
        }
    }
    __syncthreads();
}

// per-mw index set (thread (tx,ty) owns rows w0+ty+4*mw, float4-col tx)
#define MW_IDX \
    const int w   = w0 + ty + mw*ROWS_PER_PASS; \
    const int q   = tx; \
    const int nf  = w*NQ + q; \
    const int lf  = (w - w0)*NQ + q; \
    const int n   = w*N1 + q*4; \
    const int nfm = (w - 1)*NQ + q; \
    const int nfp = (w + 1)*NQ + q; \
    (void)n; (void)nfm; (void)nfp; (void)lf;

#define STENCIL4(OUT, koo, kmo, kpo, kom, kop, fc, fl, fr, fm, fp) \
    OUT.x = koo.x*fc.x + kmo.x*fl   + kom.x*fm.x + kop.x*fp.x + kpo.x*fc.y; \
    OUT.y = koo.y*fc.y + kmo.y*fc.x + kom.y*fm.y + kop.y*fp.y + kpo.y*fc.z; \
    OUT.z = koo.z*fc.z + kmo.z*fc.y + kom.z*fm.z + kop.z*fp.z + kpo.z*fc.w; \
    OUT.w = koo.w*fc.w + kmo.w*fc.z + kom.w*fm.w + kop.w*fp.w + kpo.w*fr;

#define DOT4(a,b) ((a).x*(b).x + (a).y*(b).y + (a).z*(b).z + (a).w*(b).w)
// o = a - c*b, componentwise
#define FMS4(o,a,c,b) \
    o.x = a.x - c*b.x; o.y = a.y - c*b.y; o.z = a.z - c*b.z; o.w = a.w - c*b.w;

__global__ void __launch_bounds__(TPB,1)
bicg_solver(const float* __restrict__ Vg, const float* __restrict__ M1g,
            const float* __restrict__ M2g, float* __restrict__ outg)
{
    cg::cluster_group cluster = cg::this_cluster();
    const int tid   = threadIdx.x;
    const int rank  = cluster.block_rank();
    const int batch = blockIdx.x / CLUSTER;
    const int tx = tid % NQ;
    const int ty = tid / NQ;
    const int w0 = rank * ROWS_PER_CTA;

    const float* __restrict__ Vb  = Vg  + batch*NPTS;
    const float* __restrict__ M1b = M1g + batch*NPTS;
    const float* __restrict__ M2b = M2g + batch*NPTS;
    float* __restrict__ x   = g_x [batch];
    float* __restrict__ r   = g_r [batch];
    float* __restrict__ r0  = g_r0[batch];
    float* __restrict__ p   = g_p [batch];
    float* __restrict__ v   = g_v [batch];

    // CTA-private stencil coefficients: smem only (immune to L1 flush).
    extern __shared__ float4 cs[];
    float4* __restrict__ Scoo = cs;
    float4* __restrict__ Scmo = cs + 1*F4_PER_CTA;
    float4* __restrict__ Scpo = cs + 2*F4_PER_CTA;
    float4* __restrict__ Scom = cs + 3*F4_PER_CTA;
    float4* __restrict__ Scop = cs + 4*F4_PER_CTA;

    // Register-resident vector slices (this thread's 6 float4s of each array)
    float4 Rp[MWN], Rv[MWN], Rrs[MWN], Rt[MWN], Rr0[MWN];

    __shared__ double s_part[2*NCH];
    __shared__ double s_out[NCH];
    int red_idx = 0;
    float vals[NCH];

    // ---------- mean(V_batch) ----------
    {
        float acc = 0.0f;
        const float4* vc4 = CAS4(Vb) + rank*F4_PER_CTA;
        #pragma unroll
        for (int k2 = 0; k2 < F4_ITERS; k2++) {
            float4 vv = vc4[k2*TPB + tid];
            acc += (vv.x + vv.y) + (vv.z + vv.w);
        }
        vals[0] = acc;
        cluster_reduce(cluster, vals, 1, s_part, s_out, red_idx & 1); red_idx++;
    }
    const float bval = (float)(s_out[0] * (1.0/(double)NPTS)) + 1.0f;

    // ---------- stencil coefficients (smem) + init ----------
    float accp = 0.0f;
    #pragma unroll
    for (int mw = 0; mw < MWN; mw++) {
        MW_IDX
        const int wmr = (w > 0)      ? w - 1 : w;
        const int wpr = (w < N1 - 1) ? w + 1 : w;
        float4 Vc = CAS4(Vb)[nf];
        float4 Vm = CAS4(Vb)[wmr*NQ + q];
        float4 Vp = CAS4(Vb)[wpr*NQ + q];
        float  vl = (q > 0)     ? Vb[n-1] : 0.0f;
        float  vr = (q < NQ-1)  ? Vb[n+4] : 0.0f;
        float4 M1c = CAS4(M1b)[nf];
        float  m1l = (q > 0)    ? M1b[n-1] : 0.0f;
        float4 M2c = CAS4(M2b)[nf];
        float4 M2m = CAS4(M2b)[wmr*NQ + q];
        float cv[6]  = {vl, Vc.x, Vc.y, Vc.z, Vc.w, vr};
        float m1a[5] = {m1l, M1c.x, M1c.y, M1c.z, M1c.w};
        float vmv[4] = {Vm.x, Vm.y, Vm.z, Vm.w};
        float vpv[4] = {Vp.x, Vp.y, Vp.z, Vp.w};
        float m2c[4] = {M2c.x, M2c.y, M2c.z, M2c.w};
        float m2m[4] = {M2m.x, M2m.y, M2m.z, M2m.w};
        float4 koo, kmo, kpo, kom, kop, pn4, x4;
        float* koo_ = &koo.x; float* kmo_ = &kmo.x; float* kpo_ = &kpo.x;
        float* kom_ = &kom.x; float* kop_ = &kop.x; float* pn_ = &pn4.x; float* x_ = &x4.x;
        #pragma unroll
        for (int i = 0; i < 4; i++) {
            int u = q*4 + i;
            float d1p = 0.f, d1m = 0.f, d2p = 0.f, d2m = 0.f;
            if (u < N1-1) d1p = (cv[i+2]-cv[i+1])/(0.5f*(cv[i+2]+cv[i+1])+1.0f)*m1a[i+1];
            if (u > 0)    d1m = (cv[i+1]-cv[i]  )/(0.5f*(cv[i+1]+cv[i]  )+1.0f)*m1a[i];
            if (w < N1-1) d2p = (vpv[i]-cv[i+1] )/(0.5f*(vpv[i]+cv[i+1] )+1.0f)*m2c[i];
            if (w > 0)    d2m = (cv[i+1]-vmv[i] )/(0.5f*(cv[i+1]+vmv[i] )+1.0f)*m2m[i];
            float a_po = -10.0f + 5.0f*d1p;
            float a_mo = -10.0f - 5.0f*d1m;
            float a_op = -10.0f + 5.0f*d2p;
            float a_om = -10.0f - 5.0f*d2m;
            float a_oo = 81.0f + a_po + a_mo + a_op + a_om;
            kpo_[i] = a_po; kmo_[i] = a_mo; kop_[i] = a_op; kom_[i] = a_om; koo_[i] = a_oo;
            float pn = bval*(1.0f - (a_oo + a_mo + a_po + a_om + a_op));
            pn_[i] = pn; x_[i] = bval;
            accp += pn * pn;
        }
        Scoo[lf] = koo; Scmo[lf] = kmo; Scpo[lf] = kpo;
        Scom[lf] = kom; Scop[lf] = kop;
        Rp[mw] = pn4; Rrs[mw] = pn4; Rr0[mw] = pn4;
        AS4(p)[nf] = pn4; AS4(r)[nf] = pn4; AS4(r0)[nf] = pn4; AS4(x)[nf] = x4;
    }
    vals[0] = accp;
    cluster_reduce(cluster, vals, 1, s_part, s_out, red_idx & 1); red_idx++;
    double pp = s_out[0];
    double r0_abs = (pp > 0.0) ? sqrt(pp) : 0.0;
    double r_abs  = r0_abs;
    double srr0   = pp;
    const double thr = 1e-9 * (double)NPTS;

    // ---------- BiCGSTAB main loop ----------
    for (int it = 0; it < KMAXI; it++) {
        if (!(r_abs > thr)) break;

        // P1: v = A p (center from regs, neighbors from global); sigma, ||v||^2
        float a0 = 0.f, a1 = 0.f;
        #pragma unroll
        for (int mw = 0; mw < MWN; mw++) {
            MW_IDX
            float4 pc = Rp[mw];
            float4 pm = (w > 0)      ? CAS4(p)[nfm] : pc;
            float4 pq = (w < N1 - 1) ? CAS4(p)[nfp] : pc;
            float  pl = (q > 0)      ? p[n-1] : pc.x;
            float  pr = (q < NQ-1)   ? p[n+4] : pc.w;
            float4 koo = Scoo[lf], kmo = Scmo[lf], kpo = Scpo[lf];
            float4 kom = Scom[lf], kop = Scop[lf];
            float4 vn;
            STENCIL4(vn, koo, kmo, kpo, kom, kop, pc, pl, pr, pm, pq);
            Rv[mw] = vn;
            AS4(v)[nf] = vn;
            a0 += DOT4(vn, Rr0[mw]);
            a1 += DOT4(vn, vn);
        }
        vals[0] = a0; vals[1] = a1;
        cluster_reduce(cluster, vals, 2, s_part, s_out, red_idx & 1); red_idx++;
        double sigma = s_out[0];
        double vsq   = s_out[1];
        double v_abs = (vsq > 0.0) ? sqrt(vsq) : 0.0;

        if (sigma <= 1e-9 * v_abs * r0_abs) {    // restart (R1)
            float ar = 0.f;
            #pragma unroll
            for (int mw = 0; mw < MWN; mw++) {
                MW_IDX
                float4 xc = CAS4(x)[nf];
                float4 xm = (w > 0)      ? CAS4(x)[nfm] : xc;
                float4 xq = (w < N1 - 1) ? CAS4(x)[nfp] : xc;
                float  xl = (q > 0)      ? x[n-1] : xc.x;
                float  xr = (q < NQ-1)   ? x[n+4] : xc.w;
                float4 koo = Scoo[lf], kmo = Scmo[lf], kpo = Scpo[lf];
                float4 kom = Scom[lf], kop = Scop[lf];
                float4 ax;
                STENCIL4(ax, koo, kmo, kpo, kom, kop, xc, xl, xr, xm, xq);
                float4 pn;
                pn.x = bval - ax.x; pn.y = bval - ax.y; pn.z = bval - ax.z; pn.w = bval - ax.w;
                Rp[mw] = pn; Rrs[mw] = pn; Rr0[mw] = pn;
                AS4(p)[nf] = pn; AS4(r)[nf] = pn; AS4(r0)[nf] = pn;
                ar += DOT4(pn, pn);
            }
            vals[0] = ar;
            cluster_reduce(cluster, vals, 1, s_part, s_out, red_idx & 1); red_idx++;
            double rr = s_out[0];
            r0_abs = (rr > 0.0) ? sqrt(rr) : 0.0;
            r_abs  = r0_abs;
            srr0   = rr;
            continue;
        }

        double alpha  = srr0 / sigma;
        float  af = (float)alpha;

        // P2: s = r - alpha*v (center regs; halos from global r,v), t = A s (regs);
        // acc ||s||^2, <t,s>, <t,t>. No stores.
        float b0 = 0.f, b1 = 0.f, b2 = 0.f;
        #pragma unroll
        for (int mw = 0; mw < MWN; mw++) {
            MW_IDX
            float4 sc; FMS4(sc, Rrs[mw], af, Rv[mw]);
            float4 sm, sq;
            if (w > 0) {
                float4 rm = CAS4(r)[nfm], vm = CAS4(v)[nfm];
                FMS4(sm, rm, af, vm);
            } else sm = sc;
            if (w < N1 - 1) {
                float4 rq = CAS4(r)[nfp], vq = CAS4(v)[nfp];
                FMS4(sq, rq, af, vq);
            } else sq = sc;
            float sl = (q > 0)    ? (r[n-1] - af*v[n-1]) : sc.x;
            float sr = (q < NQ-1) ? (r[n+4] - af*v[n+4]) : sc.w;
            float4 koo = Scoo[lf], kmo = Scmo[lf], kpo = Scpo[lf];
            float4 kom = Scom[lf], kop = Scop[lf];
            float4 tn;
            STENCIL4(tn, koo, kmo, kpo, kom, kop, sc, sl, sr, sm, sq);
            Rt[mw] = tn; Rrs[mw] = sc;
            b0 += DOT4(sc, sc);
            b1 += DOT4(tn, sc);
            b2 += DOT4(tn, tn);
        }
        vals[0] = b0; vals[1] = b1; vals[2] = b2;
        cluster_reduce(cluster, vals, 3, s_part, s_out, red_idx & 1); red_idx++;
        double ssum = s_out[0];
        double tsv  = s_out[1];
        double ttv  = s_out[2];
        double s_abs = (ssum > 0.0) ? sqrt(ssum) : 0.0;

        if (s_abs <= thr) {                      // C2/C3: converged
            #pragma unroll
            for (int mw = 0; mw < MWN; mw++) {
                MW_IDX
                float4 xc = CAS4(x)[nf];
                float4 pc = Rp[mw];
                xc.x += af*pc.x; xc.y += af*pc.y; xc.z += af*pc.z; xc.w += af*pc.w;
                AS4(x)[nf] = xc;
            }
            r_abs = s_abs;
            break;
        }

        double omega = tsv / ttv;
        float  of = (float)omega;

        // P3 reduction: pure register math (rn = s - omega*t; r0 in regs)
        float c0a = 0.f, c1a = 0.f;
        #pragma unroll
        for (int mw = 0; mw < MWN; mw++) {
            float4 rn; FMS4(rn, Rrs[mw], of, Rt[mw]);
            c0a += DOT4(rn, Rr0[mw]);
            c1a += DOT4(rn, rn);
        }
        vals[0] = c0a; vals[1] = c1a;
        cluster_reduce(cluster, vals, 2, s_part, s_out, red_idx & 1); red_idx++;
        double rnr0 = s_out[0], rn2 = s_out[1];
        double beta = (alpha / omega) * (rnr0 / srr0);
        float  bf = (float)beta;
        srr0  = rnr0;
        r_abs = (rn2 > 0.0) ? sqrt(rn2) : 0.0;

        // Store sweep (fused P3+P4): x += af*p + of*s; r = s - of*t;
        // p = r + bf*(p - of*v). Only x center loaded.
        #pragma unroll
        for (int mw = 0; mw < MWN; mw++) {
            MW_IDX
            float4 xc = CAS4(x)[nf];
            float4 sc = Rrs[mw], tn = Rt[mw], pc = Rp[mw], vn = Rv[mw];
            float4 rn; FMS4(rn, sc, of, tn);
            float4 xn;
            xn.x = xc.x + af*pc.x + of*sc.x;
            xn.y = xc.y + af*pc.y + of*sc.y;
            xn.z = xc.z + af*pc.z + of*sc.z;
            xn.w = xc.w + af*pc.w + of*sc.w;
            float4 pn;
            pn.x = rn.x + bf*(pc.x - of*vn.x);
            pn.y = rn.y + bf*(pc.y - of*vn.y);
            pn.z = rn.z + bf*(pc.z - of*vn.z);
            pn.w = rn.w + bf*(pc.w - of*vn.w);
            Rrs[mw] = rn; Rp[mw] = pn;
            AS4(x)[nf] = xn; AS4(r)[nf] = rn; AS4(p)[nf] = pn;
        }
        cluster.sync();   // order x/r/p writes before next iteration's halo reads
    }

    cluster.sync();       // x fully written & visible across the cluster

    // ---------- output: out[b][i][j] = x[j*384 + i] (transposed frame) ----------
    float* outb = outg + batch*NPTS;
    #pragma unroll 1
    for (int k2 = 0; k2 < PTS_PER_CTA/TPB; k2++) {
        int lin = k2*TPB + tid;
        int ul  = lin / N1;
        int wq  = lin - ul*N1;
        int uo  = w0 + ul;
        outb[uo*N1 + wq] = x[wq*N1 + uo];
    }
}

extern "C" void kernel_launch(void* const* d_in, const int* in_sizes, int n_in,
                              void* d_out, int out_size)
{
    const float* V  = (const float*)d_in[0];
    const float* M1 = (const float*)d_in[1];
    const float* M2 = (const float*)d_in[2];
    float* out = (float*)d_out;

    cudaFuncSetAttribute(bicg_solver, cudaFuncAttributeNonPortableClusterSizeAllowed, 1);
    cudaFuncSetAttribute(bicg_solver, cudaFuncAttributeMaxDynamicSharedMemorySize,
                         SMEM_COEF_BYTES);

    cudaLaunchConfig_t cfg = {};
    cfg.gridDim  = dim3(NB*CLUSTER, 1, 1);
    cfg.blockDim = dim3(TPB, 1, 1);
    cfg.dynamicSmemBytes = SMEM_COEF_BYTES;
    cudaLaunchAttribute attrs[1];
    attrs[0].id = cudaLaunchAttributeClusterDimension;
    attrs[0].val.clusterDim.x = CLUSTER;
    attrs[0].val.clusterDim.y = 1;
    attrs[0].val.clusterDim.z = 1;
    cfg.attrs = attrs;
    cfg.numAttrs = 1;
    cudaLaunchKernelEx(&cfg, bicg_solver, V, M1, M2, out);
}